// round 9
// baseline (speedup 1.0000x reference)
#include <cuda_runtime.h>
#include <cuda_bf16.h>
#include <cstdint>
#include <math.h>

#define BB    4096
#define INF_  2048
#define FEATF 2048
#define EE    512
#define NSN   1024
#define INV_T 10.0f

// ---------------- scratch ----------------------------------------------------
__device__ __nv_bfloat16 g_x2 [(size_t)BB   * 2 * INF_ ];
__device__ __nv_bfloat16 g_w1 [(size_t)FEATF* 2 * INF_ ];
__device__ __nv_bfloat16 g_w2 [(size_t)EE   * 2 * FEATF];
__device__ __nv_bfloat16 g_f2 [(size_t)BB   * 2 * FEATF];
__device__ float         g_zsp[(size_t)2 * BB * EE];        // split-K halves
__device__ __nv_bfloat16 g_nz2[(size_t)BB * 2 * EE];
__device__ float         g_ns [(size_t)NSN * EE];
__device__ __nv_bfloat16 g_ns2[(size_t)NSN * 2 * EE];
__device__ float         g_scores[(size_t)BB * NSN];        // raw cosine dots
__device__ unsigned long long g_amax[BB];
__device__ int           g_cnt[NSN];
__device__ float         g_p2[(size_t)NSN * 8 * 3];         // abssim CE partials
__device__ float         g_d2[NSN];
__device__ float         g_rl1[BB];
__device__ float         g_rl2[NSN];

// ---------------- helpers ----------------------------------------------------
__device__ __forceinline__ uint32_t smem_u32(const void* p) {
    uint32_t a;
    asm("{ .reg .u64 t; cvta.to.shared.u64 t, %1; cvt.u32.u64 %0, t; }" : "=r"(a) : "l"(p));
    return a;
}
__device__ __forceinline__ void cpasync16(uint32_t dst, const void* src) {
    asm volatile("cp.async.cg.shared.global [%0], [%1], 16;" :: "r"(dst), "l"(src) : "memory");
}
#define CP_COMMIT() asm volatile("cp.async.commit_group;" ::: "memory")
#define CP_WAIT(n)  asm volatile("cp.async.wait_group %0;" :: "n"(n) : "memory")

__device__ __forceinline__ void ldm_x4(uint32_t& r0, uint32_t& r1, uint32_t& r2, uint32_t& r3,
                                       uint32_t addr) {
    asm volatile("ldmatrix.sync.aligned.m8n8.x4.shared.b16 {%0,%1,%2,%3}, [%4];"
                 : "=r"(r0), "=r"(r1), "=r"(r2), "=r"(r3) : "r"(addr));
}
__device__ __forceinline__ void mma16816(float* c, const uint32_t* a, const uint32_t* b) {
    asm volatile(
        "mma.sync.aligned.m16n8k16.row.col.f32.bf16.bf16.f32 "
        "{%0,%1,%2,%3},{%4,%5,%6,%7},{%8,%9},{%0,%1,%2,%3};"
        : "+f"(c[0]), "+f"(c[1]), "+f"(c[2]), "+f"(c[3])
        : "r"(a[0]), "r"(a[1]), "r"(a[2]), "r"(a[3]), "r"(b[0]), "r"(b[1]));
}
__device__ __forceinline__ uint32_t swz(int row, int c) {
    return (uint32_t)(((row >> 1) << 7) + ((((((row & 1) << 2) | c)) ^ ((row >> 1) & 7)) << 4));
}
__device__ __forceinline__ unsigned long long packkey(float v, int col) {
    uint32_t u = __float_as_uint(v);
    u = (u & 0x80000000u) ? ~u : (u | 0x80000000u);
    return ((unsigned long long)u << 32) | (uint32_t)(~col);
}

__device__ __forceinline__ float blkRedSum(float v) {
    __shared__ float sh[33];
    int lane = threadIdx.x & 31, w = threadIdx.x >> 5;
    #pragma unroll
    for (int o = 16; o > 0; o >>= 1) v += __shfl_xor_sync(0xffffffffu, v, o);
    if (lane == 0) sh[w] = v;
    __syncthreads();
    int nw = blockDim.x >> 5;
    v = (threadIdx.x < (unsigned)nw) ? sh[threadIdx.x] : 0.f;
    if (w == 0) {
        #pragma unroll
        for (int o = 16; o > 0; o >>= 1) v += __shfl_xor_sync(0xffffffffu, v, o);
        if (lane == 0) sh[32] = v;
    }
    __syncthreads();
    float r = sh[32];
    __syncthreads();
    return r;
}

// ---------------- fast exp on FMA pipe ---------------------------------------
__device__ __forceinline__ float fexp(float x) {
    float y = x * 1.4426950408889634f;
    float m = y + 12582912.0f;
    float i = m - 12582912.0f;
    float r = y - i;
    float p = 9.61812910762848e-3f;
    p = fmaf(p, r, 5.55041086648216e-2f);
    p = fmaf(p, r, 2.40226506959101e-1f);
    p = fmaf(p, r, 6.93147180559945e-1f);
    p = fmaf(p, r, 1.0f);
    int sc = (__float_as_int(m) - 0x4B400000 + 127) << 23;
    return p * __int_as_float(sc);
}

// =============================================================================
// bf16 split GEMM, 256 threads (8 warps 4x2), BM=BN=128, BK=32, 5 stages.
// PASSES=3: Ahi*Bhi + Ahi*Blo + Alo*Bhi. PASSES=1: hi only. SPLITK via blockIdx.z.
// MODE 0: Cf[z*zstride + ...] = scale*D
// MODE 2: relu(D + bias) -> bf16 hi/lo into C2
// MODE 3: fused CE partials    MODE 4: store raw D + fused argmax
// =============================================================================
template<int MODE, int PASSES, int SPLITK>
__global__ __launch_bounds__(256, 2)
void gemm_k(const __nv_bfloat16* __restrict__ A, int ldA,
            const __nv_bfloat16* __restrict__ B, int ldB,
            int K, int Ncols,
            const float* __restrict__ bias, float scale,
            float* __restrict__ Cf, size_t zstride,
            __nv_bfloat16* __restrict__ C2, int ldC2, int loOff,
            float* __restrict__ P, int nbx, float* __restrict__ Dg,
            unsigned long long* __restrict__ amax)
{
    constexpr int STAGES = 5;
    constexpr int MI = 2, NI = 8;            // warp tile 32x64
    constexpr uint32_t STAGE = 16384;

    extern __shared__ __align__(128) char smraw[];
    const uint32_t sm0 = smem_u32(smraw);

    const int tid  = threadIdx.x;
    const int wid  = tid >> 5;
    const int lane = tid & 31;
    const int wm   = wid >> 1;
    const int wn   = wid & 1;

    const int bm = blockIdx.y * 128;
    const int bn = blockIdx.x * 128;
    const int nc = K >> 5;
    const int half = nc / SPLITK;
    const int zid = (SPLITK > 1) ? blockIdx.z : 0;
    const int total = PASSES * half;

    float acc[MI][NI][4];
    #pragma unroll
    for (int i = 0; i < MI; i++)
        #pragma unroll
        for (int j = 0; j < NI; j++)
            #pragma unroll
            for (int q = 0; q < 4; q++) acc[i][j][q] = 0.f;

    auto load_stage = [&](int t, int buf) {
        int p = t / half, cc = zid * half + (t - p * half);
        long acol = (p == 2 ? (long)K : 0) + (long)cc * 32;
        long bcol = (p == 1 ? (long)K : 0) + (long)cc * 32;
        uint32_t aB = sm0 + buf * STAGE;
        uint32_t bBs = aB + 8192;
        #pragma unroll
        for (int i = 0; i < 2; i++) {
            int u = tid + i * 256; int r = u >> 2, c = u & 3;
            cpasync16(aB + swz(r, c), A + (long)(bm + r) * ldA + acol + c * 8);
        }
        #pragma unroll
        for (int i = 0; i < 2; i++) {
            int u = tid + i * 256; int r = u >> 2, c = u & 3;
            cpasync16(bBs + swz(r, c), B + (long)(bn + r) * ldB + bcol + c * 8);
        }
    };

    auto compute_stage = [&](int buf) {
        uint32_t aB = sm0 + buf * STAGE;
        uint32_t bB = aB + 8192;
        #pragma unroll
        for (int ks = 0; ks < 2; ks++) {
            uint32_t af[MI][4], bf[NI][2];
            int cch = ks * 2 + (lane >> 4);
            #pragma unroll
            for (int mi = 0; mi < MI; mi++) {
                int r = wm * 32 + mi * 16 + (lane & 15);
                ldm_x4(af[mi][0], af[mi][1], af[mi][2], af[mi][3], aB + swz(r, cch));
            }
            #pragma unroll
            for (int nj = 0; nj < NI / 2; nj++) {
                int r = wn * 64 + nj * 16 + (lane & 15);
                uint32_t q0, q1, q2, q3;
                ldm_x4(q0, q1, q2, q3, bB + swz(r, cch));
                bf[2 * nj][0] = q0; bf[2 * nj + 1][0] = q1;
                bf[2 * nj][1] = q2; bf[2 * nj + 1][1] = q3;
            }
            #pragma unroll
            for (int mi = 0; mi < MI; mi++)
                #pragma unroll
                for (int ni = 0; ni < NI; ni++)
                    mma16816(acc[mi][ni], af[mi], bf[ni]);
        }
    };

    #pragma unroll
    for (int s = 0; s < STAGES - 1; s++) { load_stage(s, s); CP_COMMIT(); }

    for (int t = 0; t < total; t++) {
        CP_WAIT(STAGES - 2);
        __syncthreads();
        if (t + STAGES - 1 < total) {
            load_stage(t + STAGES - 1, (t + STAGES - 1) % STAGES);
            CP_COMMIT();
        }
        compute_stage(t % STAGES);
    }

    if (MODE == 3) {
        float S[MI][2][3];
        #pragma unroll
        for (int mi = 0; mi < MI; mi++)
            #pragma unroll
            for (int h = 0; h < 2; h++)
                #pragma unroll
                for (int s = 0; s < 3; s++) S[mi][h][s] = 0.f;
        #pragma unroll
        for (int mi = 0; mi < MI; mi++) {
            int r0 = bm + wm * 32 + mi * 16 + (lane >> 2);
            #pragma unroll
            for (int ni = 0; ni < NI; ni++) {
                int c0 = bn + wn * 64 + ni * 8 + 2 * (lane & 3);
                #pragma unroll
                for (int q = 0; q < 4; q++) {
                    int gr = r0 + (q >> 1) * 8;
                    int gc = c0 + (q & 1);
                    float e = __expf(fmaf(acc[mi][ni][q], scale, -10.f));
                    if (gr == gc) Dg[gr] = e;
                    float e2 = e * e;
                    S[mi][q >> 1][0] += e;
                    S[mi][q >> 1][1] += e2;
                    S[mi][q >> 1][2] = fmaf(e2, e, S[mi][q >> 1][2]);
                }
            }
        }
        #pragma unroll
        for (int mi = 0; mi < MI; mi++)
            #pragma unroll
            for (int h = 0; h < 2; h++)
                #pragma unroll
                for (int s = 0; s < 3; s++) {
                    float v = S[mi][h][s];
                    v += __shfl_xor_sync(0xffffffffu, v, 1);
                    v += __shfl_xor_sync(0xffffffffu, v, 2);
                    S[mi][h][s] = v;
                }
        __syncthreads();
        float* sums = (float*)smraw;
        if ((lane & 3) == 0) {
            #pragma unroll
            for (int mi = 0; mi < MI; mi++)
                #pragma unroll
                for (int h = 0; h < 2; h++) {
                    int rib = wm * 32 + mi * 16 + (lane >> 2) + h * 8;
                    #pragma unroll
                    for (int s = 0; s < 3; s++)
                        sums[(wn * 128 + rib) * 3 + s] = S[mi][h][s];
                }
        }
        __syncthreads();
        if (tid < 128) {
            #pragma unroll
            for (int s = 0; s < 3; s++)
                P[((size_t)(bm + tid) * nbx + blockIdx.x) * 3 + s] =
                    sums[tid * 3 + s] + sums[(128 + tid) * 3 + s];
        }
        return;
    }

    if (MODE == 4) {
        #pragma unroll
        for (int mi = 0; mi < MI; mi++) {
            int r0 = bm + wm * 32 + mi * 16 + (lane >> 2);
            #pragma unroll
            for (int ni = 0; ni < NI; ni++) {
                int c0 = bn + wn * 64 + ni * 8 + 2 * (lane & 3);
                float2 u0 = { acc[mi][ni][0], acc[mi][ni][1] };
                float2 u1 = { acc[mi][ni][2], acc[mi][ni][3] };
                *(float2*)(Cf + (long)r0 * Ncols + c0) = u0;
                *(float2*)(Cf + (long)(r0 + 8) * Ncols + c0) = u1;
            }
        }
        #pragma unroll
        for (int mi = 0; mi < MI; mi++) {
            int r0 = bm + wm * 32 + mi * 16 + (lane >> 2);
            #pragma unroll
            for (int h = 0; h < 2; h++) {
                unsigned long long key = 0;
                #pragma unroll
                for (int ni = 0; ni < NI; ni++) {
                    int c0 = bn + wn * 64 + ni * 8 + 2 * (lane & 3);
                    unsigned long long k0 = packkey(acc[mi][ni][h * 2 + 0], c0);
                    unsigned long long k1 = packkey(acc[mi][ni][h * 2 + 1], c0 + 1);
                    if (k0 > key) key = k0;
                    if (k1 > key) key = k1;
                }
                #pragma unroll
                for (int o = 1; o <= 2; o <<= 1) {
                    unsigned long long ok = __shfl_xor_sync(0xffffffffu, key, o);
                    if (ok > key) key = ok;
                }
                if ((lane & 3) == 0) atomicMax(amax + r0 + h * 8, key);
            }
        }
        return;
    }

    #pragma unroll
    for (int mi = 0; mi < MI; mi++) {
        int r0 = bm + wm * 32 + mi * 16 + (lane >> 2);
        #pragma unroll
        for (int ni = 0; ni < NI; ni++) {
            int c0 = bn + wn * 64 + ni * 8 + 2 * (lane & 3);
            float d0 = acc[mi][ni][0], d1 = acc[mi][ni][1];
            float d2 = acc[mi][ni][2], d3 = acc[mi][ni][3];
            if (MODE == 0) {
                float* o = Cf + (size_t)zid * zstride;
                float2 u0 = { d0 * scale, d1 * scale };
                float2 u1 = { d2 * scale, d3 * scale };
                *(float2*)(o + (long)r0 * Ncols + c0) = u0;
                *(float2*)(o + (long)(r0 + 8) * Ncols + c0) = u1;
            } else if (MODE == 2) {
                float b0 = __ldg(bias + c0), b1 = __ldg(bias + c0 + 1);
                float v0 = fmaxf(d0 + b0, 0.f), v1 = fmaxf(d1 + b1, 0.f);
                float v2 = fmaxf(d2 + b0, 0.f), v3 = fmaxf(d3 + b1, 0.f);
                __nv_bfloat16 h0 = __float2bfloat16(v0), h1 = __float2bfloat16(v1);
                __nv_bfloat16 h2 = __float2bfloat16(v2), h3 = __float2bfloat16(v3);
                __nv_bfloat16 l0 = __float2bfloat16(v0 - __bfloat162float(h0));
                __nv_bfloat16 l1 = __float2bfloat16(v1 - __bfloat162float(h1));
                __nv_bfloat16 l2 = __float2bfloat16(v2 - __bfloat162float(h2));
                __nv_bfloat16 l3 = __float2bfloat16(v3 - __bfloat162float(h3));
                __nv_bfloat162 hp0; hp0.x = h0; hp0.y = h1;
                __nv_bfloat162 hp1; hp1.x = h2; hp1.y = h3;
                __nv_bfloat162 lp0; lp0.x = l0; lp0.y = l1;
                __nv_bfloat162 lp1; lp1.x = l2; lp1.y = l3;
                *(__nv_bfloat162*)(C2 + (long)r0 * ldC2 + c0) = hp0;
                *(__nv_bfloat162*)(C2 + (long)(r0 + 8) * ldC2 + c0) = hp1;
                *(__nv_bfloat162*)(C2 + (long)r0 * ldC2 + loOff + c0) = lp0;
                *(__nv_bfloat162*)(C2 + (long)(r0 + 8) * ldC2 + loOff + c0) = lp1;
            }
        }
    }
}

// ---------------- fp32 -> bf16 hi/lo split -----------------------------------
__global__ void cvt_split(const float4* __restrict__ in, __nv_bfloat16* __restrict__ out,
                          int kshift, int n4)
{
    int i = blockIdx.x * blockDim.x + threadIdx.x;
    if (i >= n4) return;
    float4 v = in[i];
    long e = (long)i * 4;
    int K = 1 << kshift;
    long r = e >> kshift;
    int k = (int)(e & (K - 1));
    long base = r * (2L * K) + k;
    float f[4] = {v.x, v.y, v.z, v.w};
    __nv_bfloat16 h[4], l[4];
    #pragma unroll
    for (int j = 0; j < 4; j++) {
        h[j] = __float2bfloat16(f[j]);
        l[j] = __float2bfloat16(f[j] - __bfloat162float(h[j]));
    }
    __nv_bfloat162 p0; p0.x = h[0]; p0.y = h[1];
    __nv_bfloat162 p1; p1.x = h[2]; p1.y = h[3];
    __nv_bfloat162 q0; q0.x = l[0]; q0.y = l[1];
    __nv_bfloat162 q1; q1.x = l[2]; q1.y = l[3];
    *(__nv_bfloat162*)(out + base + 0) = p0;
    *(__nv_bfloat162*)(out + base + 2) = p1;
    *(__nv_bfloat162*)(out + base + K + 0) = q0;
    *(__nv_bfloat162*)(out + base + K + 2) = q1;
}

// ---------------- l2 normalize + split ---------------------------------------
__global__ void l2norm_split(const float* __restrict__ in,
                             __nv_bfloat16* __restrict__ out2,
                             float* __restrict__ outf)
{
    int row = blockIdx.x;
    const float4* p = (const float4*)(in + (long)row * EE);
    float4 v = p[threadIdx.x];
    float ss = v.x*v.x + v.y*v.y + v.z*v.z + v.w*v.w;
    float tot = blkRedSum(ss);
    float s = 1.f / fmaxf(sqrtf(tot), 1e-12f);
    v.x *= s; v.y *= s; v.z *= s; v.w *= s;
    if (outf) ((float4*)(outf + (long)row * EE))[threadIdx.x] = v;
    long base = (long)row * (2 * EE) + threadIdx.x * 4;
    float f[4] = {v.x, v.y, v.z, v.w};
    __nv_bfloat16 h[4], l[4];
    #pragma unroll
    for (int j = 0; j < 4; j++) {
        h[j] = __float2bfloat16(f[j]);
        l[j] = __float2bfloat16(f[j] - __bfloat162float(h[j]));
    }
    __nv_bfloat162 p0; p0.x = h[0]; p0.y = h[1];
    __nv_bfloat162 p1; p1.x = h[2]; p1.y = h[3];
    __nv_bfloat162 q0; q0.x = l[0]; q0.y = l[1];
    __nv_bfloat162 q1; q1.x = l[2]; q1.y = l[3];
    *(__nv_bfloat162*)(out2 + base + 0) = p0;
    *(__nv_bfloat162*)(out2 + base + 2) = p1;
    *(__nv_bfloat162*)(out2 + base + EE + 0) = q0;
    *(__nv_bfloat162*)(out2 + base + EE + 2) = q1;
}

// ---------------- merge split-K halves + bias, normalize, split --------------
__global__ void l2norm_merge(const float* __restrict__ za, const float* __restrict__ zb,
                             const float* __restrict__ bias,
                             __nv_bfloat16* __restrict__ out2)
{
    int row = blockIdx.x;
    float4 a = ((const float4*)(za + (long)row * EE))[threadIdx.x];
    float4 b = ((const float4*)(zb + (long)row * EE))[threadIdx.x];
    float4 c = ((const float4*)bias)[threadIdx.x];
    float4 v = { a.x + b.x + c.x, a.y + b.y + c.y, a.z + b.z + c.z, a.w + b.w + c.w };
    float ss = v.x*v.x + v.y*v.y + v.z*v.z + v.w*v.w;
    float tot = blkRedSum(ss);
    float s = 1.f / fmaxf(sqrtf(tot), 1e-12f);
    v.x *= s; v.y *= s; v.z *= s; v.w *= s;
    long base = (long)row * (2 * EE) + threadIdx.x * 4;
    float f[4] = {v.x, v.y, v.z, v.w};
    __nv_bfloat16 h[4], l[4];
    #pragma unroll
    for (int j = 0; j < 4; j++) {
        h[j] = __float2bfloat16(f[j]);
        l[j] = __float2bfloat16(f[j] - __bfloat162float(h[j]));
    }
    __nv_bfloat162 p0; p0.x = h[0]; p0.y = h[1];
    __nv_bfloat162 p1; p1.x = h[2]; p1.y = h[3];
    __nv_bfloat162 q0; q0.x = l[0]; q0.y = l[1];
    __nv_bfloat162 q1; q1.x = l[2]; q1.y = l[3];
    *(__nv_bfloat162*)(out2 + base + 0) = p0;
    *(__nv_bfloat162*)(out2 + base + 2) = p1;
    *(__nv_bfloat162*)(out2 + base + EE + 0) = q0;
    *(__nv_bfloat162*)(out2 + base + EE + 2) = q1;
}

// ---------------- init -------------------------------------------------------
__global__ void init_bufs(unsigned long long* a, int n, int* cnt, int m)
{
    int i = blockIdx.x * blockDim.x + threadIdx.x;
    if (i < n) a[i] = 0ull;
    if (i < m) cnt[i] = 0;
}

// ---------------- fused: histogram + output gather ---------------------------
__global__ void hist_gather(float* __restrict__ out, const float* __restrict__ ns,
                            const unsigned long long* __restrict__ amax,
                            int* __restrict__ cnt)
{
    int row = blockIdx.x;
    int idx = (int)(~(uint32_t)(amax[row] & 0xffffffffull));
    if (threadIdx.x == 0) atomicAdd(cnt + idx, 1);
    ((float4*)(out + (long)row * EE))[threadIdx.x] =
        ((const float4*)(ns + (long)idx * EE))[threadIdx.x];
}

// ---------------- compat CE via histogram-weighted scores pass ---------------
__global__ __launch_bounds__(256)
void compat_ce(const float* __restrict__ S, const int* __restrict__ cnt,
               const unsigned long long* __restrict__ amax, float* __restrict__ rl)
{
    int row = blockIdx.x;
    const float* p = S + (size_t)row * NSN;
    float S1 = 0.f, S2 = 0.f, S3 = 0.f;
    #pragma unroll
    for (int it = 0; it < NSN / 256; it++) {
        int k = threadIdx.x + it * 256;
        float c = (float)cnt[k];
        float s = fmaf(p[k], INV_T, -10.f);
        float e = (it & 1) ? fexp(s) : __expf(s);
        float ce = c * e;
        S1 += ce;
        S2 += ce * e;
        S3 += ce * e * e;
    }
    S1 = blkRedSum(S1);
    S2 = blkRedSum(S2);
    S3 = blkRedSum(S3);
    if (threadIdx.x == 0) {
        int idx = (int)(~(uint32_t)(amax[row] & 0xffffffffull));
        float ed = __expf(fmaf(p[idx], INV_T, -10.f));
        float Z = S1;
        float t = (float)BB + 1.0f + S2 / (2.0f * Z * Z) + S3 / (6.0f * Z * Z * Z);
        rl[row] = -(ed / Z - logf(t));
    }
}

// ---------------- CE finish (abssim) -----------------------------------------
__global__ void ce_finish(const float* __restrict__ P, int nbx,
                          const float* __restrict__ Dg, int cols,
                          float* __restrict__ rl, int rows)
{
    int r = blockIdx.x * blockDim.x + threadIdx.x;
    if (r >= rows) return;
    float S1 = 0.f, S2 = 0.f, S3 = 0.f;
    const float* p = P + (size_t)r * nbx * 3;
    for (int b = 0; b < nbx; b++) {
        S1 += p[b * 3 + 0];
        S2 += p[b * 3 + 1];
        S3 += p[b * 3 + 2];
    }
    float Z = S1;
    float t = (float)cols + 1.0f + S2 / (2.0f * Z * Z) + S3 / (6.0f * Z * Z * Z);
    float pd = Dg[r] / Z;
    rl[r] = -(pd - logf(t));
}

// ---------------- final loss -------------------------------------------------
__global__ void final_loss(float* __restrict__ out, long idx)
{
    float s1 = 0.f;
    for (int i = threadIdx.x; i < BB; i += 1024) s1 += g_rl1[i];
    float s2 = (threadIdx.x < NSN) ? g_rl2[threadIdx.x] : 0.f;
    float v = s1 * (1.0f / (float)BB) + s2 * (1.0f / (float)NSN);
    v = blkRedSum(v);
    if (threadIdx.x == 0) out[idx] = v;
}

// ---------------- launch ------------------------------------------------------
extern "C" void kernel_launch(void* const* d_in, const int* in_sizes, int n_in,
                              void* d_out, int out_size)
{
    const float* x          = (const float*)d_in[0];
    const float* body_W     = (const float*)d_in[1];
    const float* body_b     = (const float*)d_in[2];
    const float* fc_W       = (const float*)d_in[3];
    const float* fc_b       = (const float*)d_in[4];
    const float* abs_states = (const float*)d_in[5];
    float* out = (float*)d_out;

    __nv_bfloat16 *x2, *w1, *w2, *f2, *nz2, *ns2;
    float *zsp, *ns, *scores, *p2, *d2, *rl1, *rl2;
    unsigned long long* amax;
    int* cnt;
    cudaGetSymbolAddress((void**)&x2,  g_x2);
    cudaGetSymbolAddress((void**)&w1,  g_w1);
    cudaGetSymbolAddress((void**)&w2,  g_w2);
    cudaGetSymbolAddress((void**)&f2,  g_f2);
    cudaGetSymbolAddress((void**)&zsp, g_zsp);
    cudaGetSymbolAddress((void**)&nz2, g_nz2);
    cudaGetSymbolAddress((void**)&ns,  g_ns);
    cudaGetSymbolAddress((void**)&ns2, g_ns2);
    cudaGetSymbolAddress((void**)&scores, g_scores);
    cudaGetSymbolAddress((void**)&amax, g_amax);
    cudaGetSymbolAddress((void**)&cnt, g_cnt);
    cudaGetSymbolAddress((void**)&p2,  g_p2);
    cudaGetSymbolAddress((void**)&d2,  g_d2);
    cudaGetSymbolAddress((void**)&rl1, g_rl1);
    cudaGetSymbolAddress((void**)&rl2, g_rl2);

    static cudaStream_t s2 = nullptr, s3 = nullptr;
    static cudaEvent_t eRoot = nullptr, eW1 = nullptr, eW2 = nullptr,
                       eNS2 = nullptr, eSc = nullptr, eAbs = nullptr;
    if (!s2) {
        cudaStreamCreateWithFlags(&s2, cudaStreamNonBlocking);
        cudaStreamCreateWithFlags(&s3, cudaStreamNonBlocking);
        cudaEventCreateWithFlags(&eRoot, cudaEventDisableTiming);
        cudaEventCreateWithFlags(&eW1, cudaEventDisableTiming);
        cudaEventCreateWithFlags(&eW2, cudaEventDisableTiming);
        cudaEventCreateWithFlags(&eNS2, cudaEventDisableTiming);
        cudaEventCreateWithFlags(&eSc, cudaEventDisableTiming);
        cudaEventCreateWithFlags(&eAbs, cudaEventDisableTiming);
    }

    const int SMEMB = 5 * 16384;             // 80 KB, 2 CTAs/SM = 160 KB
    cudaFuncSetAttribute(gemm_k<2,3,1>, cudaFuncAttributeMaxDynamicSharedMemorySize, SMEMB);
    cudaFuncSetAttribute(gemm_k<0,3,2>, cudaFuncAttributeMaxDynamicSharedMemorySize, SMEMB);
    cudaFuncSetAttribute(gemm_k<4,3,1>, cudaFuncAttributeMaxDynamicSharedMemorySize, SMEMB);
    cudaFuncSetAttribute(gemm_k<3,1,1>, cudaFuncAttributeMaxDynamicSharedMemorySize, SMEMB);

    const size_t ZST = (size_t)BB * EE;

    // ---- root fork: conversions in parallel across 3 streams
    init_bufs<<<(BB + 255) / 256, 256>>>(amax, BB, cnt, NSN);
    cudaEventRecord(eRoot, 0);
    cudaStreamWaitEvent(s2, eRoot, 0);
    cudaStreamWaitEvent(s3, eRoot, 0);

    // s3: body_W conversion (parallel with cvt_x on s0)
    cvt_split<<<(FEATF * INF_ / 4 + 255) / 256, 256, 0, s3>>>(
        (const float4*)body_W, w1, 11, FEATF * INF_ / 4);
    cudaEventRecord(eW1, s3);

    // s2: abs_states normalize + fc_W conversion (hides under cvt_x / G1 start)
    l2norm_split<<<NSN, 128, 0, s2>>>(abs_states, ns2, ns);
    cudaEventRecord(eNS2, s2);
    cvt_split<<<(EE * FEATF / 4 + 255) / 256, 256, 0, s2>>>(
        (const float4*)fc_W, w2, 11, EE * FEATF / 4);
    cudaEventRecord(eW2, s2);

    // s0: x conversion (overlaps w1 conversion on s3)
    cvt_split<<<(BB * INF_ / 4 + 255) / 256, 256>>>((const float4*)x, x2, 11, BB * INF_ / 4);

    // 1) feat = relu(x @ body_W^T + b) -> split bf16
    cudaStreamWaitEvent(0, eW1, 0);
    gemm_k<2,3,1><<<dim3(FEATF / 128, BB / 128), 256, SMEMB>>>(
        x2, 2 * INF_, w1, 2 * INF_, INF_, FEATF, body_b, 1.f,
        nullptr, 0, f2, 2 * FEATF, FEATF, nullptr, 0, nullptr, nullptr);

    // 2) z = feat @ fc_W^T (split-K=2)
    cudaStreamWaitEvent(0, eW2, 0);
    gemm_k<0,3,2><<<dim3(EE / 128, BB / 128, 2), 256, SMEMB>>>(
        f2, 2 * FEATF, w2, 2 * FEATF, FEATF, EE, nullptr, 1.f,
        zsp, ZST, nullptr, 0, 0, nullptr, 0, nullptr, nullptr);

    // 3) merge halves + fc_b, normalize, split
    l2norm_merge<<<BB, 128>>>(zsp, zsp + ZST, fc_b, nz2);

    // 4) scores (stored raw) + fused argmax
    cudaStreamWaitEvent(0, eNS2, 0);
    gemm_k<4,3,1><<<dim3(NSN / 128, BB / 128), 256, SMEMB>>>(
        nz2, 2 * EE, ns2, 2 * EE, EE, NSN, nullptr, 1.f,
        scores, 0, nullptr, 0, 0, nullptr, 0, nullptr, amax);
    cudaEventRecord(eSc, 0);

    // s2: abssim CE branch in the TAIL — tensor pipe is idle during compat_ce
    cudaStreamWaitEvent(s2, eSc, 0);
    gemm_k<3,1,1><<<dim3(NSN / 128, NSN / 128), 256, SMEMB, s2>>>(
        ns2, 2 * EE, ns2, 2 * EE, EE, NSN, nullptr, INV_T,
        nullptr, 0, nullptr, 0, 0, p2, 8, d2, nullptr);
    ce_finish<<<(NSN + 255) / 256, 256, 0, s2>>>(p2, 8, d2, NSN, rl2, NSN);
    cudaEventRecord(eAbs, s2);

    // s0: fused histogram + output gather, then compat CE from scores
    hist_gather<<<BB, 128>>>(out, ns, amax, cnt);
    compat_ce<<<BB, 256>>>(scores, cnt, amax, rl1);

    // join + final loss
    cudaStreamWaitEvent(0, eAbs, 0);
    if (out_size > BB * EE) {
        final_loss<<<1, 1024>>>(out, (long)BB * EE);
    }
}

// round 10
// speedup vs baseline: 1.1309x; 1.1309x over previous
#include <cuda_runtime.h>
#include <cuda_bf16.h>
#include <cstdint>
#include <math.h>

#define BB    4096
#define INF_  2048
#define FEATF 2048
#define EE    512
#define NSN   1024
#define INV_T 10.0f

// ---------------- scratch ----------------------------------------------------
__device__ __nv_bfloat16 g_x2 [(size_t)BB   * 2 * INF_ ];
__device__ __nv_bfloat16 g_w1 [(size_t)FEATF* 2 * INF_ ];
__device__ __nv_bfloat16 g_w2 [(size_t)EE   * 2 * FEATF];
__device__ __nv_bfloat16 g_f2 [(size_t)BB   * 2 * FEATF];
__device__ float         g_zsp[(size_t)2 * BB * EE];        // split-K halves
__device__ __nv_bfloat16 g_nz2[(size_t)BB * 2 * EE];
__device__ float         g_ns [(size_t)NSN * EE];
__device__ __nv_bfloat16 g_ns2[(size_t)NSN * 2 * EE];
__device__ float         g_scores[(size_t)BB * NSN];        // raw cosine dots
__device__ unsigned long long g_amax[BB];
__device__ int           g_cnt[NSN];
__device__ float         g_p2[(size_t)NSN * 8 * 3];         // abssim CE partials
__device__ float         g_d2[NSN];
__device__ float         g_rl1[BB];
__device__ float         g_rl2[NSN];

// ---------------- helpers ----------------------------------------------------
__device__ __forceinline__ uint32_t smem_u32(const void* p) {
    uint32_t a;
    asm("{ .reg .u64 t; cvta.to.shared.u64 t, %1; cvt.u32.u64 %0, t; }" : "=r"(a) : "l"(p));
    return a;
}
__device__ __forceinline__ void cpasync16(uint32_t dst, const void* src) {
    asm volatile("cp.async.cg.shared.global [%0], [%1], 16;" :: "r"(dst), "l"(src) : "memory");
}
#define CP_COMMIT() asm volatile("cp.async.commit_group;" ::: "memory")
#define CP_WAIT(n)  asm volatile("cp.async.wait_group %0;" :: "n"(n) : "memory")

__device__ __forceinline__ void ldm_x4(uint32_t& r0, uint32_t& r1, uint32_t& r2, uint32_t& r3,
                                       uint32_t addr) {
    asm volatile("ldmatrix.sync.aligned.m8n8.x4.shared.b16 {%0,%1,%2,%3}, [%4];"
                 : "=r"(r0), "=r"(r1), "=r"(r2), "=r"(r3) : "r"(addr));
}
__device__ __forceinline__ void mma16816(float* c, const uint32_t* a, const uint32_t* b) {
    asm volatile(
        "mma.sync.aligned.m16n8k16.row.col.f32.bf16.bf16.f32 "
        "{%0,%1,%2,%3},{%4,%5,%6,%7},{%8,%9},{%0,%1,%2,%3};"
        : "+f"(c[0]), "+f"(c[1]), "+f"(c[2]), "+f"(c[3])
        : "r"(a[0]), "r"(a[1]), "r"(a[2]), "r"(a[3]), "r"(b[0]), "r"(b[1]));
}
// 128B-row SW128 swizzle: byte offset for (row, 16B-chunk c of 8)
__device__ __forceinline__ uint32_t swz(int row, int c) {
    return (uint32_t)((row << 7) + (((c ^ (row & 7)) << 4)));
}
__device__ __forceinline__ unsigned long long packkey(float v, int col) {
    uint32_t u = __float_as_uint(v);
    u = (u & 0x80000000u) ? ~u : (u | 0x80000000u);
    return ((unsigned long long)u << 32) | (uint32_t)(~col);
}

__device__ __forceinline__ float blkRedSum(float v) {
    __shared__ float sh[33];
    int lane = threadIdx.x & 31, w = threadIdx.x >> 5;
    #pragma unroll
    for (int o = 16; o > 0; o >>= 1) v += __shfl_xor_sync(0xffffffffu, v, o);
    if (lane == 0) sh[w] = v;
    __syncthreads();
    int nw = blockDim.x >> 5;
    v = (threadIdx.x < (unsigned)nw) ? sh[threadIdx.x] : 0.f;
    if (w == 0) {
        #pragma unroll
        for (int o = 16; o > 0; o >>= 1) v += __shfl_xor_sync(0xffffffffu, v, o);
        if (lane == 0) sh[32] = v;
    }
    __syncthreads();
    float r = sh[32];
    __syncthreads();
    return r;
}

// ---------------- fast exp on FMA pipe ---------------------------------------
__device__ __forceinline__ float fexp(float x) {
    float y = x * 1.4426950408889634f;
    float m = y + 12582912.0f;
    float i = m - 12582912.0f;
    float r = y - i;
    float p = 9.61812910762848e-3f;
    p = fmaf(p, r, 5.55041086648216e-2f);
    p = fmaf(p, r, 2.40226506959101e-1f);
    p = fmaf(p, r, 6.93147180559945e-1f);
    p = fmaf(p, r, 1.0f);
    int sc = (__float_as_int(m) - 0x4B400000 + 127) << 23;
    return p * __int_as_float(sc);
}

// =============================================================================
// bf16 split GEMM, 256 threads (8 warps 4x2), BM=BN=128, BK=64, 3 stages.
// PASSES=3: Ahi*Bhi + Ahi*Blo + Alo*Bhi. PASSES=1: hi only. SPLITK via blockIdx.z.
// MODE 0: Cf[z*zstride + ...] = scale*D
// MODE 2: relu(D + bias) -> bf16 hi/lo into C2
// MODE 3: fused CE partials    MODE 4: store raw D + fused argmax
// =============================================================================
template<int MODE, int PASSES, int SPLITK>
__global__ __launch_bounds__(256, 2)
void gemm_k(const __nv_bfloat16* __restrict__ A, int ldA,
            const __nv_bfloat16* __restrict__ B, int ldB,
            int K, int Ncols,
            const float* __restrict__ bias, float scale,
            float* __restrict__ Cf, size_t zstride,
            __nv_bfloat16* __restrict__ C2, int ldC2, int loOff,
            float* __restrict__ P, int nbx, float* __restrict__ Dg,
            unsigned long long* __restrict__ amax)
{
    constexpr int STAGES = 3;
    constexpr int MI = 2, NI = 8;            // warp tile 32x64
    constexpr uint32_t ATILE = 16384;        // 128 rows * 128 B
    constexpr uint32_t STAGE = 2 * ATILE;    // A + B

    extern __shared__ __align__(128) char smraw[];
    const uint32_t sm0 = smem_u32(smraw);

    const int tid  = threadIdx.x;
    const int wid  = tid >> 5;
    const int lane = tid & 31;
    const int wm   = wid >> 1;
    const int wn   = wid & 1;

    const int bm = blockIdx.y * 128;
    const int bn = blockIdx.x * 128;
    const int nc = K >> 6;                   // 64-wide K chunks per pass
    const int half = nc / SPLITK;
    const int zid = (SPLITK > 1) ? blockIdx.z : 0;
    const int total = PASSES * half;

    float acc[MI][NI][4];
    #pragma unroll
    for (int i = 0; i < MI; i++)
        #pragma unroll
        for (int j = 0; j < NI; j++)
            #pragma unroll
            for (int q = 0; q < 4; q++) acc[i][j][q] = 0.f;

    auto load_stage = [&](int t, int buf) {
        int p = t / half, cc = zid * half + (t - p * half);
        long acol = (p == 2 ? (long)K : 0) + (long)cc * 64;
        long bcol = (p == 1 ? (long)K : 0) + (long)cc * 64;
        uint32_t aB = sm0 + buf * STAGE;
        uint32_t bBs = aB + ATILE;
        #pragma unroll
        for (int i = 0; i < 4; i++) {
            int u = tid + i * 256; int r = u >> 3, c = u & 7;
            cpasync16(aB + swz(r, c), A + (long)(bm + r) * ldA + acol + c * 8);
        }
        #pragma unroll
        for (int i = 0; i < 4; i++) {
            int u = tid + i * 256; int r = u >> 3, c = u & 7;
            cpasync16(bBs + swz(r, c), B + (long)(bn + r) * ldB + bcol + c * 8);
        }
    };

    auto compute_stage = [&](int buf) {
        uint32_t aB = sm0 + buf * STAGE;
        uint32_t bB = aB + ATILE;
        #pragma unroll
        for (int ks = 0; ks < 4; ks++) {
            uint32_t af[MI][4], bf[NI][2];
            int cch = ks * 2 + (lane >> 4);
            #pragma unroll
            for (int mi = 0; mi < MI; mi++) {
                int r = wm * 32 + mi * 16 + (lane & 15);
                ldm_x4(af[mi][0], af[mi][1], af[mi][2], af[mi][3], aB + swz(r, cch));
            }
            #pragma unroll
            for (int nj = 0; nj < NI / 2; nj++) {
                int r = wn * 64 + nj * 16 + (lane & 15);
                uint32_t q0, q1, q2, q3;
                ldm_x4(q0, q1, q2, q3, bB + swz(r, cch));
                bf[2 * nj][0] = q0; bf[2 * nj + 1][0] = q1;
                bf[2 * nj][1] = q2; bf[2 * nj + 1][1] = q3;
            }
            #pragma unroll
            for (int mi = 0; mi < MI; mi++)
                #pragma unroll
                for (int ni = 0; ni < NI; ni++)
                    mma16816(acc[mi][ni], af[mi], bf[ni]);
        }
    };

    #pragma unroll
    for (int s = 0; s < STAGES - 1; s++) { load_stage(s, s); CP_COMMIT(); }

    for (int t = 0; t < total; t++) {
        CP_WAIT(STAGES - 2);
        __syncthreads();
        if (t + STAGES - 1 < total) {
            load_stage(t + STAGES - 1, (t + STAGES - 1) % STAGES);
            CP_COMMIT();
        }
        compute_stage(t % STAGES);
    }

    if (MODE == 3) {
        float S[MI][2][3];
        #pragma unroll
        for (int mi = 0; mi < MI; mi++)
            #pragma unroll
            for (int h = 0; h < 2; h++)
                #pragma unroll
                for (int s = 0; s < 3; s++) S[mi][h][s] = 0.f;
        #pragma unroll
        for (int mi = 0; mi < MI; mi++) {
            int r0 = bm + wm * 32 + mi * 16 + (lane >> 2);
            #pragma unroll
            for (int ni = 0; ni < NI; ni++) {
                int c0 = bn + wn * 64 + ni * 8 + 2 * (lane & 3);
                #pragma unroll
                for (int q = 0; q < 4; q++) {
                    int gr = r0 + (q >> 1) * 8;
                    int gc = c0 + (q & 1);
                    float e = __expf(fmaf(acc[mi][ni][q], scale, -10.f));
                    if (gr == gc) Dg[gr] = e;
                    float e2 = e * e;
                    S[mi][q >> 1][0] += e;
                    S[mi][q >> 1][1] += e2;
                    S[mi][q >> 1][2] = fmaf(e2, e, S[mi][q >> 1][2]);
                }
            }
        }
        #pragma unroll
        for (int mi = 0; mi < MI; mi++)
            #pragma unroll
            for (int h = 0; h < 2; h++)
                #pragma unroll
                for (int s = 0; s < 3; s++) {
                    float v = S[mi][h][s];
                    v += __shfl_xor_sync(0xffffffffu, v, 1);
                    v += __shfl_xor_sync(0xffffffffu, v, 2);
                    S[mi][h][s] = v;
                }
        __syncthreads();
        float* sums = (float*)smraw;
        if ((lane & 3) == 0) {
            #pragma unroll
            for (int mi = 0; mi < MI; mi++)
                #pragma unroll
                for (int h = 0; h < 2; h++) {
                    int rib = wm * 32 + mi * 16 + (lane >> 2) + h * 8;
                    #pragma unroll
                    for (int s = 0; s < 3; s++)
                        sums[(wn * 128 + rib) * 3 + s] = S[mi][h][s];
                }
        }
        __syncthreads();
        if (tid < 128) {
            #pragma unroll
            for (int s = 0; s < 3; s++)
                P[((size_t)(bm + tid) * nbx + blockIdx.x) * 3 + s] =
                    sums[tid * 3 + s] + sums[(128 + tid) * 3 + s];
        }
        return;
    }

    if (MODE == 4) {
        #pragma unroll
        for (int mi = 0; mi < MI; mi++) {
            int r0 = bm + wm * 32 + mi * 16 + (lane >> 2);
            #pragma unroll
            for (int ni = 0; ni < NI; ni++) {
                int c0 = bn + wn * 64 + ni * 8 + 2 * (lane & 3);
                float2 u0 = { acc[mi][ni][0], acc[mi][ni][1] };
                float2 u1 = { acc[mi][ni][2], acc[mi][ni][3] };
                *(float2*)(Cf + (long)r0 * Ncols + c0) = u0;
                *(float2*)(Cf + (long)(r0 + 8) * Ncols + c0) = u1;
            }
        }
        #pragma unroll
        for (int mi = 0; mi < MI; mi++) {
            int r0 = bm + wm * 32 + mi * 16 + (lane >> 2);
            #pragma unroll
            for (int h = 0; h < 2; h++) {
                unsigned long long key = 0;
                #pragma unroll
                for (int ni = 0; ni < NI; ni++) {
                    int c0 = bn + wn * 64 + ni * 8 + 2 * (lane & 3);
                    unsigned long long k0 = packkey(acc[mi][ni][h * 2 + 0], c0);
                    unsigned long long k1 = packkey(acc[mi][ni][h * 2 + 1], c0 + 1);
                    if (k0 > key) key = k0;
                    if (k1 > key) key = k1;
                }
                #pragma unroll
                for (int o = 1; o <= 2; o <<= 1) {
                    unsigned long long ok = __shfl_xor_sync(0xffffffffu, key, o);
                    if (ok > key) key = ok;
                }
                if ((lane & 3) == 0) atomicMax(amax + r0 + h * 8, key);
            }
        }
        return;
    }

    #pragma unroll
    for (int mi = 0; mi < MI; mi++) {
        int r0 = bm + wm * 32 + mi * 16 + (lane >> 2);
        #pragma unroll
        for (int ni = 0; ni < NI; ni++) {
            int c0 = bn + wn * 64 + ni * 8 + 2 * (lane & 3);
            float d0 = acc[mi][ni][0], d1 = acc[mi][ni][1];
            float d2 = acc[mi][ni][2], d3 = acc[mi][ni][3];
            if (MODE == 0) {
                float* o = Cf + (size_t)zid * zstride;
                float2 u0 = { d0 * scale, d1 * scale };
                float2 u1 = { d2 * scale, d3 * scale };
                *(float2*)(o + (long)r0 * Ncols + c0) = u0;
                *(float2*)(o + (long)(r0 + 8) * Ncols + c0) = u1;
            } else if (MODE == 2) {
                float b0 = __ldg(bias + c0), b1 = __ldg(bias + c0 + 1);
                float v0 = fmaxf(d0 + b0, 0.f), v1 = fmaxf(d1 + b1, 0.f);
                float v2 = fmaxf(d2 + b0, 0.f), v3 = fmaxf(d3 + b1, 0.f);
                __nv_bfloat16 h0 = __float2bfloat16(v0), h1 = __float2bfloat16(v1);
                __nv_bfloat16 h2 = __float2bfloat16(v2), h3 = __float2bfloat16(v3);
                __nv_bfloat16 l0 = __float2bfloat16(v0 - __bfloat162float(h0));
                __nv_bfloat16 l1 = __float2bfloat16(v1 - __bfloat162float(h1));
                __nv_bfloat16 l2 = __float2bfloat16(v2 - __bfloat162float(h2));
                __nv_bfloat16 l3 = __float2bfloat16(v3 - __bfloat162float(h3));
                __nv_bfloat162 hp0; hp0.x = h0; hp0.y = h1;
                __nv_bfloat162 hp1; hp1.x = h2; hp1.y = h3;
                __nv_bfloat162 lp0; lp0.x = l0; lp0.y = l1;
                __nv_bfloat162 lp1; lp1.x = l2; lp1.y = l3;
                *(__nv_bfloat162*)(C2 + (long)r0 * ldC2 + c0) = hp0;
                *(__nv_bfloat162*)(C2 + (long)(r0 + 8) * ldC2 + c0) = hp1;
                *(__nv_bfloat162*)(C2 + (long)r0 * ldC2 + loOff + c0) = lp0;
                *(__nv_bfloat162*)(C2 + (long)(r0 + 8) * ldC2 + loOff + c0) = lp1;
            }
        }
    }
}

// ---------------- fp32 -> bf16 hi/lo split -----------------------------------
__global__ void cvt_split(const float4* __restrict__ in, __nv_bfloat16* __restrict__ out,
                          int kshift, int n4)
{
    int i = blockIdx.x * blockDim.x + threadIdx.x;
    if (i >= n4) return;
    float4 v = in[i];
    long e = (long)i * 4;
    int K = 1 << kshift;
    long r = e >> kshift;
    int k = (int)(e & (K - 1));
    long base = r * (2L * K) + k;
    float f[4] = {v.x, v.y, v.z, v.w};
    __nv_bfloat16 h[4], l[4];
    #pragma unroll
    for (int j = 0; j < 4; j++) {
        h[j] = __float2bfloat16(f[j]);
        l[j] = __float2bfloat16(f[j] - __bfloat162float(h[j]));
    }
    __nv_bfloat162 p0; p0.x = h[0]; p0.y = h[1];
    __nv_bfloat162 p1; p1.x = h[2]; p1.y = h[3];
    __nv_bfloat162 q0; q0.x = l[0]; q0.y = l[1];
    __nv_bfloat162 q1; q1.x = l[2]; q1.y = l[3];
    *(__nv_bfloat162*)(out + base + 0) = p0;
    *(__nv_bfloat162*)(out + base + 2) = p1;
    *(__nv_bfloat162*)(out + base + K + 0) = q0;
    *(__nv_bfloat162*)(out + base + K + 2) = q1;
}

// ---------------- l2 normalize + split ---------------------------------------
__global__ void l2norm_split(const float* __restrict__ in,
                             __nv_bfloat16* __restrict__ out2,
                             float* __restrict__ outf)
{
    int row = blockIdx.x;
    const float4* p = (const float4*)(in + (long)row * EE);
    float4 v = p[threadIdx.x];
    float ss = v.x*v.x + v.y*v.y + v.z*v.z + v.w*v.w;
    float tot = blkRedSum(ss);
    float s = 1.f / fmaxf(sqrtf(tot), 1e-12f);
    v.x *= s; v.y *= s; v.z *= s; v.w *= s;
    if (outf) ((float4*)(outf + (long)row * EE))[threadIdx.x] = v;
    long base = (long)row * (2 * EE) + threadIdx.x * 4;
    float f[4] = {v.x, v.y, v.z, v.w};
    __nv_bfloat16 h[4], l[4];
    #pragma unroll
    for (int j = 0; j < 4; j++) {
        h[j] = __float2bfloat16(f[j]);
        l[j] = __float2bfloat16(f[j] - __bfloat162float(h[j]));
    }
    __nv_bfloat162 p0; p0.x = h[0]; p0.y = h[1];
    __nv_bfloat162 p1; p1.x = h[2]; p1.y = h[3];
    __nv_bfloat162 q0; q0.x = l[0]; q0.y = l[1];
    __nv_bfloat162 q1; q1.x = l[2]; q1.y = l[3];
    *(__nv_bfloat162*)(out2 + base + 0) = p0;
    *(__nv_bfloat162*)(out2 + base + 2) = p1;
    *(__nv_bfloat162*)(out2 + base + EE + 0) = q0;
    *(__nv_bfloat162*)(out2 + base + EE + 2) = q1;
}

// ---------------- merge split-K halves + bias, normalize, split --------------
__global__ void l2norm_merge(const float* __restrict__ za, const float* __restrict__ zb,
                             const float* __restrict__ bias,
                             __nv_bfloat16* __restrict__ out2)
{
    int row = blockIdx.x;
    float4 a = ((const float4*)(za + (long)row * EE))[threadIdx.x];
    float4 b = ((const float4*)(zb + (long)row * EE))[threadIdx.x];
    float4 c = ((const float4*)bias)[threadIdx.x];
    float4 v = { a.x + b.x + c.x, a.y + b.y + c.y, a.z + b.z + c.z, a.w + b.w + c.w };
    float ss = v.x*v.x + v.y*v.y + v.z*v.z + v.w*v.w;
    float tot = blkRedSum(ss);
    float s = 1.f / fmaxf(sqrtf(tot), 1e-12f);
    v.x *= s; v.y *= s; v.z *= s; v.w *= s;
    long base = (long)row * (2 * EE) + threadIdx.x * 4;
    float f[4] = {v.x, v.y, v.z, v.w};
    __nv_bfloat16 h[4], l[4];
    #pragma unroll
    for (int j = 0; j < 4; j++) {
        h[j] = __float2bfloat16(f[j]);
        l[j] = __float2bfloat16(f[j] - __bfloat162float(h[j]));
    }
    __nv_bfloat162 p0; p0.x = h[0]; p0.y = h[1];
    __nv_bfloat162 p1; p1.x = h[2]; p1.y = h[3];
    __nv_bfloat162 q0; q0.x = l[0]; q0.y = l[1];
    __nv_bfloat162 q1; q1.x = l[2]; q1.y = l[3];
    *(__nv_bfloat162*)(out2 + base + 0) = p0;
    *(__nv_bfloat162*)(out2 + base + 2) = p1;
    *(__nv_bfloat162*)(out2 + base + EE + 0) = q0;
    *(__nv_bfloat162*)(out2 + base + EE + 2) = q1;
}

// ---------------- init -------------------------------------------------------
__global__ void init_bufs(unsigned long long* a, int n, int* cnt, int m)
{
    int i = blockIdx.x * blockDim.x + threadIdx.x;
    if (i < n) a[i] = 0ull;
    if (i < m) cnt[i] = 0;
}

// ---------------- fused: histogram + output gather ---------------------------
__global__ void hist_gather(float* __restrict__ out, const float* __restrict__ ns,
                            const unsigned long long* __restrict__ amax,
                            int* __restrict__ cnt)
{
    int row = blockIdx.x;
    int idx = (int)(~(uint32_t)(amax[row] & 0xffffffffull));
    if (threadIdx.x == 0) atomicAdd(cnt + idx, 1);
    ((float4*)(out + (long)row * EE))[threadIdx.x] =
        ((const float4*)(ns + (long)idx * EE))[threadIdx.x];
}

// ---------------- compat CE via histogram-weighted scores pass ---------------
__global__ __launch_bounds__(256)
void compat_ce(const float* __restrict__ S, const int* __restrict__ cnt,
               const unsigned long long* __restrict__ amax, float* __restrict__ rl)
{
    int row = blockIdx.x;
    const float* p = S + (size_t)row * NSN;
    float S1 = 0.f, S2 = 0.f, S3 = 0.f;
    #pragma unroll
    for (int it = 0; it < NSN / 256; it++) {
        int k = threadIdx.x + it * 256;
        float c = (float)cnt[k];
        float s = fmaf(p[k], INV_T, -10.f);
        float e = (it & 1) ? fexp(s) : __expf(s);
        float ce = c * e;
        S1 += ce;
        S2 += ce * e;
        S3 += ce * e * e;
    }
    S1 = blkRedSum(S1);
    S2 = blkRedSum(S2);
    S3 = blkRedSum(S3);
    if (threadIdx.x == 0) {
        int idx = (int)(~(uint32_t)(amax[row] & 0xffffffffull));
        float ed = __expf(fmaf(p[idx], INV_T, -10.f));
        float Z = S1;
        float t = (float)BB + 1.0f + S2 / (2.0f * Z * Z) + S3 / (6.0f * Z * Z * Z);
        rl[row] = -(ed / Z - logf(t));
    }
}

// ---------------- CE finish (abssim) -----------------------------------------
__global__ void ce_finish(const float* __restrict__ P, int nbx,
                          const float* __restrict__ Dg, int cols,
                          float* __restrict__ rl, int rows)
{
    int r = blockIdx.x * blockDim.x + threadIdx.x;
    if (r >= rows) return;
    float S1 = 0.f, S2 = 0.f, S3 = 0.f;
    const float* p = P + (size_t)r * nbx * 3;
    for (int b = 0; b < nbx; b++) {
        S1 += p[b * 3 + 0];
        S2 += p[b * 3 + 1];
        S3 += p[b * 3 + 2];
    }
    float Z = S1;
    float t = (float)cols + 1.0f + S2 / (2.0f * Z * Z) + S3 / (6.0f * Z * Z * Z);
    float pd = Dg[r] / Z;
    rl[r] = -(pd - logf(t));
}

// ---------------- final loss -------------------------------------------------
__global__ void final_loss(float* __restrict__ out, long idx)
{
    float s1 = 0.f;
    for (int i = threadIdx.x; i < BB; i += 1024) s1 += g_rl1[i];
    float s2 = (threadIdx.x < NSN) ? g_rl2[threadIdx.x] : 0.f;
    float v = s1 * (1.0f / (float)BB) + s2 * (1.0f / (float)NSN);
    v = blkRedSum(v);
    if (threadIdx.x == 0) out[idx] = v;
}

// ---------------- launch ------------------------------------------------------
extern "C" void kernel_launch(void* const* d_in, const int* in_sizes, int n_in,
                              void* d_out, int out_size)
{
    const float* x          = (const float*)d_in[0];
    const float* body_W     = (const float*)d_in[1];
    const float* body_b     = (const float*)d_in[2];
    const float* fc_W       = (const float*)d_in[3];
    const float* fc_b       = (const float*)d_in[4];
    const float* abs_states = (const float*)d_in[5];
    float* out = (float*)d_out;

    __nv_bfloat16 *x2, *w1, *w2, *f2, *nz2, *ns2;
    float *zsp, *ns, *scores, *p2, *d2, *rl1, *rl2;
    unsigned long long* amax;
    int* cnt;
    cudaGetSymbolAddress((void**)&x2,  g_x2);
    cudaGetSymbolAddress((void**)&w1,  g_w1);
    cudaGetSymbolAddress((void**)&w2,  g_w2);
    cudaGetSymbolAddress((void**)&f2,  g_f2);
    cudaGetSymbolAddress((void**)&zsp, g_zsp);
    cudaGetSymbolAddress((void**)&nz2, g_nz2);
    cudaGetSymbolAddress((void**)&ns,  g_ns);
    cudaGetSymbolAddress((void**)&ns2, g_ns2);
    cudaGetSymbolAddress((void**)&scores, g_scores);
    cudaGetSymbolAddress((void**)&amax, g_amax);
    cudaGetSymbolAddress((void**)&cnt, g_cnt);
    cudaGetSymbolAddress((void**)&p2,  g_p2);
    cudaGetSymbolAddress((void**)&d2,  g_d2);
    cudaGetSymbolAddress((void**)&rl1, g_rl1);
    cudaGetSymbolAddress((void**)&rl2, g_rl2);

    static cudaStream_t s2 = nullptr, s3 = nullptr;
    static cudaEvent_t eRoot = nullptr, eW1 = nullptr, eW2 = nullptr,
                       eNS2 = nullptr, eAbs = nullptr;
    if (!s2) {
        cudaStreamCreateWithFlags(&s2, cudaStreamNonBlocking);
        cudaStreamCreateWithFlags(&s3, cudaStreamNonBlocking);
        cudaEventCreateWithFlags(&eRoot, cudaEventDisableTiming);
        cudaEventCreateWithFlags(&eW1, cudaEventDisableTiming);
        cudaEventCreateWithFlags(&eW2, cudaEventDisableTiming);
        cudaEventCreateWithFlags(&eNS2, cudaEventDisableTiming);
        cudaEventCreateWithFlags(&eAbs, cudaEventDisableTiming);
    }

    const int SMEMB = 3 * 32768;             // 96 KB/CTA, 2 CTAs/SM = 192 KB
    cudaFuncSetAttribute(gemm_k<2,3,1>, cudaFuncAttributeMaxDynamicSharedMemorySize, SMEMB);
    cudaFuncSetAttribute(gemm_k<0,3,2>, cudaFuncAttributeMaxDynamicSharedMemorySize, SMEMB);
    cudaFuncSetAttribute(gemm_k<4,3,1>, cudaFuncAttributeMaxDynamicSharedMemorySize, SMEMB);
    cudaFuncSetAttribute(gemm_k<3,1,1>, cudaFuncAttributeMaxDynamicSharedMemorySize, SMEMB);

    const size_t ZST = (size_t)BB * EE;

    // ---- root fork: conversions in parallel across 3 streams
    init_bufs<<<(BB + 255) / 256, 256>>>(amax, BB, cnt, NSN);
    cudaEventRecord(eRoot, 0);
    cudaStreamWaitEvent(s2, eRoot, 0);
    cudaStreamWaitEvent(s3, eRoot, 0);

    // s3: body_W conversion (parallel with cvt_x on s0)
    cvt_split<<<(FEATF * INF_ / 4 + 255) / 256, 256, 0, s3>>>(
        (const float4*)body_W, w1, 11, FEATF * INF_ / 4);
    cudaEventRecord(eW1, s3);

    // s2: abs_states normalize, fc_W conversion, abssim CE branch (hides under G1)
    l2norm_split<<<NSN, 128, 0, s2>>>(abs_states, ns2, ns);
    cudaEventRecord(eNS2, s2);
    cvt_split<<<(EE * FEATF / 4 + 255) / 256, 256, 0, s2>>>(
        (const float4*)fc_W, w2, 11, EE * FEATF / 4);
    cudaEventRecord(eW2, s2);
    gemm_k<3,1,1><<<dim3(NSN / 128, NSN / 128), 256, SMEMB, s2>>>(
        ns2, 2 * EE, ns2, 2 * EE, EE, NSN, nullptr, INV_T,
        nullptr, 0, nullptr, 0, 0, p2, 8, d2, nullptr);
    ce_finish<<<(NSN + 255) / 256, 256, 0, s2>>>(p2, 8, d2, NSN, rl2, NSN);
    cudaEventRecord(eAbs, s2);

    // s0: x conversion (overlaps w1 conversion on s3)
    cvt_split<<<(BB * INF_ / 4 + 255) / 256, 256>>>((const float4*)x, x2, 11, BB * INF_ / 4);

    // 1) feat = relu(x @ body_W^T + b) -> split bf16
    cudaStreamWaitEvent(0, eW1, 0);
    gemm_k<2,3,1><<<dim3(FEATF / 128, BB / 128), 256, SMEMB>>>(
        x2, 2 * INF_, w1, 2 * INF_, INF_, FEATF, body_b, 1.f,
        nullptr, 0, f2, 2 * FEATF, FEATF, nullptr, 0, nullptr, nullptr);

    // 2) z = feat @ fc_W^T (split-K=2)
    cudaStreamWaitEvent(0, eW2, 0);
    gemm_k<0,3,2><<<dim3(EE / 128, BB / 128, 2), 256, SMEMB>>>(
        f2, 2 * FEATF, w2, 2 * FEATF, FEATF, EE, nullptr, 1.f,
        zsp, ZST, nullptr, 0, 0, nullptr, 0, nullptr, nullptr);

    // 3) merge halves + fc_b, normalize, split
    l2norm_merge<<<BB, 128>>>(zsp, zsp + ZST, fc_b, nz2);

    // 4) scores (stored raw) + fused argmax
    cudaStreamWaitEvent(0, eNS2, 0);
    gemm_k<4,3,1><<<dim3(NSN / 128, BB / 128), 256, SMEMB>>>(
        nz2, 2 * EE, ns2, 2 * EE, EE, NSN, nullptr, 1.f,
        scores, 0, nullptr, 0, 0, nullptr, 0, nullptr, amax);

    // 5) fused histogram + output gather, then compat CE from scores
    hist_gather<<<BB, 128>>>(out, ns, amax, cnt);
    compat_ce<<<BB, 256>>>(scores, cnt, amax, rl1);

    // join + final loss
    cudaStreamWaitEvent(0, eAbs, 0);
    if (out_size > BB * EE) {
        final_loss<<<1, 1024>>>(out, (long)BB * EE);
    }
}